// round 11
// baseline (speedup 1.0000x reference)
#include <cuda_runtime.h>

#define BATCH 16
#define NPIX (1024 * 1024)
#define NVEC (NPIX / 4)
#define NACC 21
#define BPG 4                     // batches per group: 48 MB src resident (proven in R6)
#define NGROUP (BATCH / BPG)      // 4 groups
#define TPB 256
#define GX 148                    // grid 592 = exactly 4 blocks/SM (occupancy limit),
                                  // one balanced wave; ~6.9 loop iterations per block

// Scratch (allocation-free per harness rules)
__device__ double g_acc[BATCH][NACC];

__global__ void zero_kernel() {
    int i = blockIdx.x * blockDim.x + threadIdx.x;
    if (i < BATCH * NACC) ((double*)g_acc)[i] = 0.0;
}

// Raw moments for batches [base, base+BPG).
// src: default loads (evict_normal -> resident in L2 for the apply kernel)
// dst: .cs streaming loads (read once)
__global__ void __launch_bounds__(TPB) reduce_kernel(const float* __restrict__ src,
                                                     const float* __restrict__ dst,
                                                     int base) {
    const int b = base + blockIdx.y;
    const float4* A0 = (const float4*)(src + (size_t)b * 3 * NPIX);
    const float4* A1 = A0 + NVEC;
    const float4* A2 = A1 + NVEC;
    const float4* B0 = (const float4*)(dst + (size_t)b * 3 * NPIX);
    const float4* B1 = B0 + NVEC;
    const float4* B2 = B1 + NVEC;

    float acc[NACC];
#pragma unroll
    for (int k = 0; k < NACC; k++) acc[k] = 0.0f;

    const int stride = GX * TPB;
    for (int i = blockIdx.x * TPB + threadIdx.x; i < NVEC; i += stride) {
        float4 a0 = A0[i], a1 = A1[i], a2 = A2[i];
        float4 b0 = __ldcs(B0 + i), b1 = __ldcs(B1 + i), b2 = __ldcs(B2 + i);
#define LANE(c)                                                                 \
        {                                                                       \
            float x0 = a0.c, x1 = a1.c, x2 = a2.c;                              \
            float y0 = b0.c, y1 = b1.c, y2 = b2.c;                              \
            acc[0] += x0;  acc[1] += x1;  acc[2] += x2;                         \
            acc[3] += y0;  acc[4] += y1;  acc[5] += y2;                         \
            acc[6]  += x0 * x0; acc[7]  += x0 * x1; acc[8]  += x0 * x2;         \
            acc[9]  += x1 * x1; acc[10] += x1 * x2; acc[11] += x2 * x2;         \
            acc[12] += y0 * x0; acc[13] += y0 * x1; acc[14] += y0 * x2;         \
            acc[15] += y1 * x0; acc[16] += y1 * x1; acc[17] += y1 * x2;         \
            acc[18] += y2 * x0; acc[19] += y2 * x1; acc[20] += y2 * x2;         \
        }
        LANE(x) LANE(y) LANE(z) LANE(w)
#undef LANE
    }

    __shared__ float s[NACC][TPB / 32];
    const int lane = threadIdx.x & 31;
    const int warp = threadIdx.x >> 5;
#pragma unroll
    for (int k = 0; k < NACC; k++) {
        float v = acc[k];
#pragma unroll
        for (int o = 16; o > 0; o >>= 1) v += __shfl_down_sync(0xffffffffu, v, o);
        if (lane == 0) s[k][warp] = v;
    }
    __syncthreads();
    if (threadIdx.x < NACC) {
        float v = 0.0f;
#pragma unroll
        for (int w = 0; w < TPB / 32; w++) v += s[threadIdx.x][w];
        atomicAdd(&g_acc[b][threadIdx.x], (double)v);
    }
}

// Apply for batches [base, base+BPG). Thread 0 of each block solves the 3x3
// system from g_acc (complete across the launch boundary), then streams.
__global__ void __launch_bounds__(TPB) apply_kernel(const float* __restrict__ src,
                                                    float* __restrict__ out,
                                                    int base) {
    const int b = base + blockIdx.y;
    __shared__ float sh_coef[12];

    if (threadIdx.x == 0) {
        const double* a = g_acc[b];
        const double n = (double)NPIX;
        double mA[3] = {a[0] / n, a[1] / n, a[2] / n};
        double mB[3] = {a[3] / n, a[4] / n, a[5] / n};
        double AA[3][3];
        AA[0][0] = a[6]  - n * mA[0] * mA[0] + 0.001;
        AA[0][1] = a[7]  - n * mA[0] * mA[1];
        AA[0][2] = a[8]  - n * mA[0] * mA[2];
        AA[1][1] = a[9]  - n * mA[1] * mA[1] + 0.001;
        AA[1][2] = a[10] - n * mA[1] * mA[2];
        AA[2][2] = a[11] - n * mA[2] * mA[2] + 0.001;
        AA[1][0] = AA[0][1]; AA[2][0] = AA[0][2]; AA[2][1] = AA[1][2];
        double BA[3][3];
#pragma unroll
        for (int i = 0; i < 3; i++)
#pragma unroll
            for (int j = 0; j < 3; j++)
                BA[i][j] = a[12 + 3 * i + j] - n * mB[i] * mA[j];

        double c00 =  (AA[1][1] * AA[2][2] - AA[1][2] * AA[2][1]);
        double c01 = -(AA[1][0] * AA[2][2] - AA[1][2] * AA[2][0]);
        double c02 =  (AA[1][0] * AA[2][1] - AA[1][1] * AA[2][0]);
        double c10 = -(AA[0][1] * AA[2][2] - AA[0][2] * AA[2][1]);
        double c11 =  (AA[0][0] * AA[2][2] - AA[0][2] * AA[2][0]);
        double c12 = -(AA[0][0] * AA[2][1] - AA[0][1] * AA[2][0]);
        double c20 =  (AA[0][1] * AA[1][2] - AA[0][2] * AA[1][1]);
        double c21 = -(AA[0][0] * AA[1][2] - AA[0][2] * AA[1][0]);
        double c22 =  (AA[0][0] * AA[1][1] - AA[0][1] * AA[1][0]);
        double det = AA[0][0] * c00 + AA[0][1] * c01 + AA[0][2] * c02;
        double id = 1.0 / det;
        double inv[3][3] = {{c00 * id, c10 * id, c20 * id},
                            {c01 * id, c11 * id, c21 * id},
                            {c02 * id, c12 * id, c22 * id}};
#pragma unroll
        for (int i = 0; i < 3; i++) {
            double xi[3];
#pragma unroll
            for (int j = 0; j < 3; j++)
                xi[j] = BA[i][0] * inv[0][j] + BA[i][1] * inv[1][j] + BA[i][2] * inv[2][j];
            sh_coef[3 * i + 0] = (float)xi[0];
            sh_coef[3 * i + 1] = (float)xi[1];
            sh_coef[3 * i + 2] = (float)xi[2];
            sh_coef[9 + i] = (float)(mB[i] - (xi[0] * mA[0] + xi[1] * mA[1] + xi[2] * mA[2]));
        }
    }
    __syncthreads();

    const float x00 = sh_coef[0], x01 = sh_coef[1], x02 = sh_coef[2];
    const float x10 = sh_coef[3], x11 = sh_coef[4], x12 = sh_coef[5];
    const float x20 = sh_coef[6], x21 = sh_coef[7], x22 = sh_coef[8];
    const float o0 = sh_coef[9], o1 = sh_coef[10], o2 = sh_coef[11];

    const float4* A0 = (const float4*)(src + (size_t)b * 3 * NPIX);
    const float4* A1 = A0 + NVEC;
    const float4* A2 = A1 + NVEC;
    float4* O0 = (float4*)(out + (size_t)b * 3 * NPIX);
    float4* O1 = O0 + NVEC;
    float4* O2 = O1 + NVEC;

    const int stride = GX * TPB;
    for (int i = blockIdx.x * TPB + threadIdx.x; i < NVEC; i += stride) {
        // src hits L2 (loaded by reduce_kernel just before); .cs = last use
        float4 a0 = __ldcs(A0 + i), a1 = __ldcs(A1 + i), a2 = __ldcs(A2 + i);
        float4 r0, r1, r2;
#define LANE(c)                                                \
        r0.c = x00 * a0.c + x01 * a1.c + x02 * a2.c + o0;      \
        r1.c = x10 * a0.c + x11 * a1.c + x12 * a2.c + o1;      \
        r2.c = x20 * a0.c + x21 * a1.c + x22 * a2.c + o2;
        LANE(x) LANE(y) LANE(z) LANE(w)
#undef LANE
        __stcs(O0 + i, r0);
        __stcs(O1 + i, r1);
        __stcs(O2 + i, r2);
    }
}

extern "C" void kernel_launch(void* const* d_in, const int* in_sizes, int n_in,
                              void* d_out, int out_size) {
    const float* src = (const float*)d_in[0];
    const float* dst = (const float*)d_in[1];
    float* out = (float*)d_out;

    zero_kernel<<<2, 256>>>();
    for (int p = 0; p < NGROUP; p++) {
        const int base = p * BPG;
        dim3 grid(GX, BPG);
        reduce_kernel<<<grid, TPB>>>(src, dst, base);
        apply_kernel<<<grid, TPB>>>(src, out, base);
    }
}

// round 12
// speedup vs baseline: 1.0142x; 1.0142x over previous
#include <cuda_runtime.h>

#define BATCH 16
#define NPIX (1024 * 1024)
#define NVEC (NPIX / 4)
#define NV8  (NPIX / 8)
#define NACC 21
#define BPG 8                     // batches per group -> only 5 launches total
#define NGROUP (BATCH / BPG)      // 2 groups
#define TPB 256
#define GXR 74                    // reduce blocks per batch: grid 592 = 4/SM, ~6.9 iters
#define GXA 148                   // apply blocks per batch: grid 1184, ~6.9 iters

// Scratch (allocation-free per harness rules)
__device__ double g_acc[BATCH][NACC];

__global__ void zero_kernel() {
    int i = blockIdx.x * blockDim.x + threadIdx.x;
    if (i < BATCH * NACC) ((double*)g_acc)[i] = 0.0;
}

// 256-bit loads with L2 eviction priority (sm_103 requires .v8.b32 for these hints)
struct f8 { float4 a, b; };

__device__ __forceinline__ f8 ld8_last(const float* p) {   // keep resident in L2
    f8 v;
    asm("ld.global.L2::evict_last.v8.b32 {%0,%1,%2,%3,%4,%5,%6,%7}, [%8];"
        : "=f"(v.a.x), "=f"(v.a.y), "=f"(v.a.z), "=f"(v.a.w),
          "=f"(v.b.x), "=f"(v.b.y), "=f"(v.b.z), "=f"(v.b.w)
        : "l"(p));
    return v;
}
__device__ __forceinline__ f8 ld8_first(const float* p) {  // stream through L2
    f8 v;
    asm("ld.global.L2::evict_first.v8.b32 {%0,%1,%2,%3,%4,%5,%6,%7}, [%8];"
        : "=f"(v.a.x), "=f"(v.a.y), "=f"(v.a.z), "=f"(v.a.w),
          "=f"(v.b.x), "=f"(v.b.y), "=f"(v.b.z), "=f"(v.b.w)
        : "l"(p));
    return v;
}

// Raw moments for batches [base, base+BPG).
// src: evict_last (pinned in L2 for the apply kernel)
// dst: evict_first (read once, minimal L2 footprint)
__global__ void __launch_bounds__(TPB, 3) reduce_kernel(const float* __restrict__ src,
                                                        const float* __restrict__ dst,
                                                        int base) {
    const int b = base + blockIdx.y;
    const float* A0 = src + (size_t)b * 3 * NPIX;
    const float* A1 = A0 + NPIX;
    const float* A2 = A1 + NPIX;
    const float* B0 = dst + (size_t)b * 3 * NPIX;
    const float* B1 = B0 + NPIX;
    const float* B2 = B1 + NPIX;

    float acc[NACC];
#pragma unroll
    for (int k = 0; k < NACC; k++) acc[k] = 0.0f;

    const int stride = GXR * TPB;
    for (int i = blockIdx.x * TPB + threadIdx.x; i < NV8; i += stride) {
        const int e = i * 8;
        f8 a0 = ld8_last(A0 + e), a1 = ld8_last(A1 + e), a2 = ld8_last(A2 + e);
        f8 b0 = ld8_first(B0 + e), b1 = ld8_first(B1 + e), b2 = ld8_first(B2 + e);
#define LANE(h, c)                                                              \
        {                                                                       \
            float x0 = a0.h.c, x1 = a1.h.c, x2 = a2.h.c;                        \
            float y0 = b0.h.c, y1 = b1.h.c, y2 = b2.h.c;                        \
            acc[0] += x0;  acc[1] += x1;  acc[2] += x2;                         \
            acc[3] += y0;  acc[4] += y1;  acc[5] += y2;                         \
            acc[6]  += x0 * x0; acc[7]  += x0 * x1; acc[8]  += x0 * x2;         \
            acc[9]  += x1 * x1; acc[10] += x1 * x2; acc[11] += x2 * x2;         \
            acc[12] += y0 * x0; acc[13] += y0 * x1; acc[14] += y0 * x2;         \
            acc[15] += y1 * x0; acc[16] += y1 * x1; acc[17] += y1 * x2;         \
            acc[18] += y2 * x0; acc[19] += y2 * x1; acc[20] += y2 * x2;         \
        }
        LANE(a, x) LANE(a, y) LANE(a, z) LANE(a, w)
        LANE(b, x) LANE(b, y) LANE(b, z) LANE(b, w)
#undef LANE
    }

    __shared__ float s[NACC][TPB / 32];
    const int lane = threadIdx.x & 31;
    const int warp = threadIdx.x >> 5;
#pragma unroll
    for (int k = 0; k < NACC; k++) {
        float v = acc[k];
#pragma unroll
        for (int o = 16; o > 0; o >>= 1) v += __shfl_down_sync(0xffffffffu, v, o);
        if (lane == 0) s[k][warp] = v;
    }
    __syncthreads();
    if (threadIdx.x < NACC) {
        float v = 0.0f;
#pragma unroll
        for (int w = 0; w < TPB / 32; w++) v += s[threadIdx.x][w];
        atomicAdd(&g_acc[b][threadIdx.x], (double)v);
    }
}

// Apply for batches [base, base+BPG). Thread 0 of each block solves the 3x3
// system from g_acc (complete across the launch boundary), then streams.
__global__ void __launch_bounds__(TPB) apply_kernel(const float* __restrict__ src,
                                                    float* __restrict__ out,
                                                    int base) {
    const int b = base + blockIdx.y;
    __shared__ float sh_coef[12];

    if (threadIdx.x == 0) {
        const double* a = g_acc[b];
        const double n = (double)NPIX;
        double mA[3] = {a[0] / n, a[1] / n, a[2] / n};
        double mB[3] = {a[3] / n, a[4] / n, a[5] / n};
        double AA[3][3];
        AA[0][0] = a[6]  - n * mA[0] * mA[0] + 0.001;
        AA[0][1] = a[7]  - n * mA[0] * mA[1];
        AA[0][2] = a[8]  - n * mA[0] * mA[2];
        AA[1][1] = a[9]  - n * mA[1] * mA[1] + 0.001;
        AA[1][2] = a[10] - n * mA[1] * mA[2];
        AA[2][2] = a[11] - n * mA[2] * mA[2] + 0.001;
        AA[1][0] = AA[0][1]; AA[2][0] = AA[0][2]; AA[2][1] = AA[1][2];
        double BA[3][3];
#pragma unroll
        for (int i = 0; i < 3; i++)
#pragma unroll
            for (int j = 0; j < 3; j++)
                BA[i][j] = a[12 + 3 * i + j] - n * mB[i] * mA[j];

        double c00 =  (AA[1][1] * AA[2][2] - AA[1][2] * AA[2][1]);
        double c01 = -(AA[1][0] * AA[2][2] - AA[1][2] * AA[2][0]);
        double c02 =  (AA[1][0] * AA[2][1] - AA[1][1] * AA[2][0]);
        double c10 = -(AA[0][1] * AA[2][2] - AA[0][2] * AA[2][1]);
        double c11 =  (AA[0][0] * AA[2][2] - AA[0][2] * AA[2][0]);
        double c12 = -(AA[0][0] * AA[2][1] - AA[0][1] * AA[2][0]);
        double c20 =  (AA[0][1] * AA[1][2] - AA[0][2] * AA[1][1]);
        double c21 = -(AA[0][0] * AA[1][2] - AA[0][2] * AA[1][0]);
        double c22 =  (AA[0][0] * AA[1][1] - AA[0][1] * AA[1][0]);
        double det = AA[0][0] * c00 + AA[0][1] * c01 + AA[0][2] * c02;
        double id = 1.0 / det;
        double inv[3][3] = {{c00 * id, c10 * id, c20 * id},
                            {c01 * id, c11 * id, c21 * id},
                            {c02 * id, c12 * id, c22 * id}};
#pragma unroll
        for (int i = 0; i < 3; i++) {
            double xi[3];
#pragma unroll
            for (int j = 0; j < 3; j++)
                xi[j] = BA[i][0] * inv[0][j] + BA[i][1] * inv[1][j] + BA[i][2] * inv[2][j];
            sh_coef[3 * i + 0] = (float)xi[0];
            sh_coef[3 * i + 1] = (float)xi[1];
            sh_coef[3 * i + 2] = (float)xi[2];
            sh_coef[9 + i] = (float)(mB[i] - (xi[0] * mA[0] + xi[1] * mA[1] + xi[2] * mA[2]));
        }
    }
    __syncthreads();

    const float x00 = sh_coef[0], x01 = sh_coef[1], x02 = sh_coef[2];
    const float x10 = sh_coef[3], x11 = sh_coef[4], x12 = sh_coef[5];
    const float x20 = sh_coef[6], x21 = sh_coef[7], x22 = sh_coef[8];
    const float o0 = sh_coef[9], o1 = sh_coef[10], o2 = sh_coef[11];

    const float4* A0 = (const float4*)(src + (size_t)b * 3 * NPIX);
    const float4* A1 = A0 + NVEC;
    const float4* A2 = A1 + NVEC;
    float4* O0 = (float4*)(out + (size_t)b * 3 * NPIX);
    float4* O1 = O0 + NVEC;
    float4* O2 = O1 + NVEC;

    const int stride = GXA * TPB;
    for (int i = blockIdx.x * TPB + threadIdx.x; i < NVEC; i += stride) {
        // src pinned in L2 by reduce's evict_last loads; .cs = last use (demotes)
        float4 a0 = __ldcs(A0 + i), a1 = __ldcs(A1 + i), a2 = __ldcs(A2 + i);
        float4 r0, r1, r2;
#define LANE(c)                                                \
        r0.c = x00 * a0.c + x01 * a1.c + x02 * a2.c + o0;      \
        r1.c = x10 * a0.c + x11 * a1.c + x12 * a2.c + o1;      \
        r2.c = x20 * a0.c + x21 * a1.c + x22 * a2.c + o2;
        LANE(x) LANE(y) LANE(z) LANE(w)
#undef LANE
        __stcs(O0 + i, r0);
        __stcs(O1 + i, r1);
        __stcs(O2 + i, r2);
    }
}

extern "C" void kernel_launch(void* const* d_in, const int* in_sizes, int n_in,
                              void* d_out, int out_size) {
    const float* src = (const float*)d_in[0];
    const float* dst = (const float*)d_in[1];
    float* out = (float*)d_out;

    zero_kernel<<<2, 256>>>();
    for (int p = 0; p < NGROUP; p++) {
        const int base = p * BPG;
        dim3 rgrid(GXR, BPG);
        reduce_kernel<<<rgrid, TPB>>>(src, dst, base);
        dim3 agrid(GXA, BPG);
        apply_kernel<<<agrid, TPB>>>(src, out, base);
    }
}

// round 13
// speedup vs baseline: 1.0326x; 1.0181x over previous
#include <cuda_runtime.h>

#define BATCH 16
#define NPIX (1024 * 1024)
#define NVEC (NPIX / 4)
#define NV8  (NPIX / 8)
#define NACC 21
#define BPG 4                     // batches per group: 48 MB src resident (proven)
#define NGROUP (BATCH / BPG)      // 4 groups
#define TPB 256
#define GXR 74                    // reduce: grid 296 = 2/SM exact, ~6.9 iters/block
#define GXA 148                   // apply:  grid 592 = 4/SM exact, ~6.9 iters/block

// Scratch (allocation-free per harness rules)
__device__ double g_acc[BATCH][NACC];

__global__ void zero_kernel() {
    int i = blockIdx.x * blockDim.x + threadIdx.x;
    if (i < BATCH * NACC) ((double*)g_acc)[i] = 0.0;
}

// 256-bit loads with L2 eviction priority (sm_103 requires .v8.b32 for these hints)
struct f8 { float4 a, b; };

__device__ __forceinline__ f8 ld8_last(const float* p) {   // keep resident in L2
    f8 v;
    asm("ld.global.L2::evict_last.v8.b32 {%0,%1,%2,%3,%4,%5,%6,%7}, [%8];"
        : "=f"(v.a.x), "=f"(v.a.y), "=f"(v.a.z), "=f"(v.a.w),
          "=f"(v.b.x), "=f"(v.b.y), "=f"(v.b.z), "=f"(v.b.w)
        : "l"(p));
    return v;
}
__device__ __forceinline__ f8 ld8_first(const float* p) {  // stream through L2
    f8 v;
    asm("ld.global.L2::evict_first.v8.b32 {%0,%1,%2,%3,%4,%5,%6,%7}, [%8];"
        : "=f"(v.a.x), "=f"(v.a.y), "=f"(v.a.z), "=f"(v.a.w),
          "=f"(v.b.x), "=f"(v.b.y), "=f"(v.b.z), "=f"(v.b.w)
        : "l"(p));
    return v;
}

// Raw moments for batches [base, base+BPG).
// src: evict_last (pinned in L2 for the apply kernel; 48 MB well under budget)
// dst: evict_first (read once, minimal L2 footprint)
__global__ void __launch_bounds__(TPB, 3) reduce_kernel(const float* __restrict__ src,
                                                        const float* __restrict__ dst,
                                                        int base) {
    const int b = base + blockIdx.y;
    const float* A0 = src + (size_t)b * 3 * NPIX;
    const float* A1 = A0 + NPIX;
    const float* A2 = A1 + NPIX;
    const float* B0 = dst + (size_t)b * 3 * NPIX;
    const float* B1 = B0 + NPIX;
    const float* B2 = B1 + NPIX;

    float acc[NACC];
#pragma unroll
    for (int k = 0; k < NACC; k++) acc[k] = 0.0f;

    const int stride = GXR * TPB;
    for (int i = blockIdx.x * TPB + threadIdx.x; i < NV8; i += stride) {
        const int e = i * 8;
        f8 a0 = ld8_last(A0 + e), a1 = ld8_last(A1 + e), a2 = ld8_last(A2 + e);
        f8 b0 = ld8_first(B0 + e), b1 = ld8_first(B1 + e), b2 = ld8_first(B2 + e);
#define LANE(h, c)                                                              \
        {                                                                       \
            float x0 = a0.h.c, x1 = a1.h.c, x2 = a2.h.c;                        \
            float y0 = b0.h.c, y1 = b1.h.c, y2 = b2.h.c;                        \
            acc[0] += x0;  acc[1] += x1;  acc[2] += x2;                         \
            acc[3] += y0;  acc[4] += y1;  acc[5] += y2;                         \
            acc[6]  += x0 * x0; acc[7]  += x0 * x1; acc[8]  += x0 * x2;         \
            acc[9]  += x1 * x1; acc[10] += x1 * x2; acc[11] += x2 * x2;         \
            acc[12] += y0 * x0; acc[13] += y0 * x1; acc[14] += y0 * x2;         \
            acc[15] += y1 * x0; acc[16] += y1 * x1; acc[17] += y1 * x2;         \
            acc[18] += y2 * x0; acc[19] += y2 * x1; acc[20] += y2 * x2;         \
        }
        LANE(a, x) LANE(a, y) LANE(a, z) LANE(a, w)
        LANE(b, x) LANE(b, y) LANE(b, z) LANE(b, w)
#undef LANE
    }

    __shared__ float s[NACC][TPB / 32];
    const int lane = threadIdx.x & 31;
    const int warp = threadIdx.x >> 5;
#pragma unroll
    for (int k = 0; k < NACC; k++) {
        float v = acc[k];
#pragma unroll
        for (int o = 16; o > 0; o >>= 1) v += __shfl_down_sync(0xffffffffu, v, o);
        if (lane == 0) s[k][warp] = v;
    }
    __syncthreads();
    if (threadIdx.x < NACC) {
        float v = 0.0f;
#pragma unroll
        for (int w = 0; w < TPB / 32; w++) v += s[threadIdx.x][w];
        atomicAdd(&g_acc[b][threadIdx.x], (double)v);
    }
}

// Apply for batches [base, base+BPG). Thread 0 of each block solves the 3x3
// system from g_acc (complete across the launch boundary), then streams.
__global__ void __launch_bounds__(TPB) apply_kernel(const float* __restrict__ src,
                                                    float* __restrict__ out,
                                                    int base) {
    const int b = base + blockIdx.y;
    __shared__ float sh_coef[12];

    if (threadIdx.x == 0) {
        const double* a = g_acc[b];
        const double n = (double)NPIX;
        double mA[3] = {a[0] / n, a[1] / n, a[2] / n};
        double mB[3] = {a[3] / n, a[4] / n, a[5] / n};
        double AA[3][3];
        AA[0][0] = a[6]  - n * mA[0] * mA[0] + 0.001;
        AA[0][1] = a[7]  - n * mA[0] * mA[1];
        AA[0][2] = a[8]  - n * mA[0] * mA[2];
        AA[1][1] = a[9]  - n * mA[1] * mA[1] + 0.001;
        AA[1][2] = a[10] - n * mA[1] * mA[2];
        AA[2][2] = a[11] - n * mA[2] * mA[2] + 0.001;
        AA[1][0] = AA[0][1]; AA[2][0] = AA[0][2]; AA[2][1] = AA[1][2];
        double BA[3][3];
#pragma unroll
        for (int i = 0; i < 3; i++)
#pragma unroll
            for (int j = 0; j < 3; j++)
                BA[i][j] = a[12 + 3 * i + j] - n * mB[i] * mA[j];

        double c00 =  (AA[1][1] * AA[2][2] - AA[1][2] * AA[2][1]);
        double c01 = -(AA[1][0] * AA[2][2] - AA[1][2] * AA[2][0]);
        double c02 =  (AA[1][0] * AA[2][1] - AA[1][1] * AA[2][0]);
        double c10 = -(AA[0][1] * AA[2][2] - AA[0][2] * AA[2][1]);
        double c11 =  (AA[0][0] * AA[2][2] - AA[0][2] * AA[2][0]);
        double c12 = -(AA[0][0] * AA[2][1] - AA[0][1] * AA[2][0]);
        double c20 =  (AA[0][1] * AA[1][2] - AA[0][2] * AA[1][1]);
        double c21 = -(AA[0][0] * AA[1][2] - AA[0][2] * AA[1][0]);
        double c22 =  (AA[0][0] * AA[1][1] - AA[0][1] * AA[1][0]);
        double det = AA[0][0] * c00 + AA[0][1] * c01 + AA[0][2] * c02;
        double id = 1.0 / det;
        double inv[3][3] = {{c00 * id, c10 * id, c20 * id},
                            {c01 * id, c11 * id, c21 * id},
                            {c02 * id, c12 * id, c22 * id}};
#pragma unroll
        for (int i = 0; i < 3; i++) {
            double xi[3];
#pragma unroll
            for (int j = 0; j < 3; j++)
                xi[j] = BA[i][0] * inv[0][j] + BA[i][1] * inv[1][j] + BA[i][2] * inv[2][j];
            sh_coef[3 * i + 0] = (float)xi[0];
            sh_coef[3 * i + 1] = (float)xi[1];
            sh_coef[3 * i + 2] = (float)xi[2];
            sh_coef[9 + i] = (float)(mB[i] - (xi[0] * mA[0] + xi[1] * mA[1] + xi[2] * mA[2]));
        }
    }
    __syncthreads();

    const float x00 = sh_coef[0], x01 = sh_coef[1], x02 = sh_coef[2];
    const float x10 = sh_coef[3], x11 = sh_coef[4], x12 = sh_coef[5];
    const float x20 = sh_coef[6], x21 = sh_coef[7], x22 = sh_coef[8];
    const float o0 = sh_coef[9], o1 = sh_coef[10], o2 = sh_coef[11];

    const float4* A0 = (const float4*)(src + (size_t)b * 3 * NPIX);
    const float4* A1 = A0 + NVEC;
    const float4* A2 = A1 + NVEC;
    float4* O0 = (float4*)(out + (size_t)b * 3 * NPIX);
    float4* O1 = O0 + NVEC;
    float4* O2 = O1 + NVEC;

    const int stride = GXA * TPB;
    for (int i = blockIdx.x * TPB + threadIdx.x; i < NVEC; i += stride) {
        // src pinned in L2 by reduce's evict_last loads; .cs = last use (demotes)
        float4 a0 = __ldcs(A0 + i), a1 = __ldcs(A1 + i), a2 = __ldcs(A2 + i);
        float4 r0, r1, r2;
#define LANE(c)                                                \
        r0.c = x00 * a0.c + x01 * a1.c + x02 * a2.c + o0;      \
        r1.c = x10 * a0.c + x11 * a1.c + x12 * a2.c + o1;      \
        r2.c = x20 * a0.c + x21 * a1.c + x22 * a2.c + o2;
        LANE(x) LANE(y) LANE(z) LANE(w)
#undef LANE
        __stcs(O0 + i, r0);
        __stcs(O1 + i, r1);
        __stcs(O2 + i, r2);
    }
}

extern "C" void kernel_launch(void* const* d_in, const int* in_sizes, int n_in,
                              void* d_out, int out_size) {
    const float* src = (const float*)d_in[0];
    const float* dst = (const float*)d_in[1];
    float* out = (float*)d_out;

    zero_kernel<<<2, 256>>>();
    for (int p = 0; p < NGROUP; p++) {
        const int base = p * BPG;
        dim3 rgrid(GXR, BPG);
        reduce_kernel<<<rgrid, TPB>>>(src, dst, base);
        dim3 agrid(GXA, BPG);
        apply_kernel<<<agrid, TPB>>>(src, out, base);
    }
}

// round 14
// speedup vs baseline: 1.1283x; 1.0926x over previous
#include <cuda_runtime.h>

#define BATCH 16
#define NPIX (1024 * 1024)
#define NVEC (NPIX / 4)
#define NV8  (NPIX / 8)
#define NACC 21
#define BPG 2                     // pipeline group size: <=48 MB evict_last live set
#define NGROUP (BATCH / BPG)      // 8 groups
#define TPB 256
#define GXA 148                   // apply blocks per batch (v4, ~6.9 iters)
#define GXR 74                    // reduce blocks per batch in combined (v8, ~6.9 iters)

// Scratch (allocation-free per harness rules)
__device__ double g_acc[BATCH][NACC];

__global__ void zero_kernel() {
    int i = blockIdx.x * blockDim.x + threadIdx.x;
    if (i < BATCH * NACC) ((double*)g_acc)[i] = 0.0;
}

// 256-bit loads with L2 eviction priority (sm_103 requires .v8.b32 for these hints)
struct f8 { float4 a, b; };

__device__ __forceinline__ f8 ld8_last(const float* p) {   // pin in L2
    f8 v;
    asm("ld.global.L2::evict_last.v8.b32 {%0,%1,%2,%3,%4,%5,%6,%7}, [%8];"
        : "=f"(v.a.x), "=f"(v.a.y), "=f"(v.a.z), "=f"(v.a.w),
          "=f"(v.b.x), "=f"(v.b.y), "=f"(v.b.z), "=f"(v.b.w)
        : "l"(p));
    return v;
}
__device__ __forceinline__ f8 ld8_first(const float* p) {  // stream through L2
    f8 v;
    asm("ld.global.L2::evict_first.v8.b32 {%0,%1,%2,%3,%4,%5,%6,%7}, [%8];"
        : "=f"(v.a.x), "=f"(v.a.y), "=f"(v.a.z), "=f"(v.a.w),
          "=f"(v.b.x), "=f"(v.b.y), "=f"(v.b.z), "=f"(v.b.w)
        : "l"(p));
    return v;
}

// ---------------- device bodies ----------------

__device__ __forceinline__ void reduce_body(const float* __restrict__ src,
                                            const float* __restrict__ dst,
                                            int b, int blk, int nblk, int tid) {
    const float* A0 = src + (size_t)b * 3 * NPIX;
    const float* A1 = A0 + NPIX;
    const float* A2 = A1 + NPIX;
    const float* B0 = dst + (size_t)b * 3 * NPIX;
    const float* B1 = B0 + NPIX;
    const float* B2 = B1 + NPIX;

    float acc[NACC];
#pragma unroll
    for (int k = 0; k < NACC; k++) acc[k] = 0.0f;

    const int stride = nblk * TPB;
    for (int i = blk * TPB + tid; i < NV8; i += stride) {
        const int e = i * 8;
        f8 a0 = ld8_last(A0 + e), a1 = ld8_last(A1 + e), a2 = ld8_last(A2 + e);
        f8 b0 = ld8_first(B0 + e), b1 = ld8_first(B1 + e), b2 = ld8_first(B2 + e);
#define LANE(h, c)                                                              \
        {                                                                       \
            float x0 = a0.h.c, x1 = a1.h.c, x2 = a2.h.c;                        \
            float y0 = b0.h.c, y1 = b1.h.c, y2 = b2.h.c;                        \
            acc[0] += x0;  acc[1] += x1;  acc[2] += x2;                         \
            acc[3] += y0;  acc[4] += y1;  acc[5] += y2;                         \
            acc[6]  += x0 * x0; acc[7]  += x0 * x1; acc[8]  += x0 * x2;         \
            acc[9]  += x1 * x1; acc[10] += x1 * x2; acc[11] += x2 * x2;         \
            acc[12] += y0 * x0; acc[13] += y0 * x1; acc[14] += y0 * x2;         \
            acc[15] += y1 * x0; acc[16] += y1 * x1; acc[17] += y1 * x2;         \
            acc[18] += y2 * x0; acc[19] += y2 * x1; acc[20] += y2 * x2;         \
        }
        LANE(a, x) LANE(a, y) LANE(a, z) LANE(a, w)
        LANE(b, x) LANE(b, y) LANE(b, z) LANE(b, w)
#undef LANE
    }

    __shared__ float s[NACC][TPB / 32];
    const int lane = tid & 31;
    const int warp = tid >> 5;
#pragma unroll
    for (int k = 0; k < NACC; k++) {
        float v = acc[k];
#pragma unroll
        for (int o = 16; o > 0; o >>= 1) v += __shfl_down_sync(0xffffffffu, v, o);
        if (lane == 0) s[k][warp] = v;
    }
    __syncthreads();
    if (tid < NACC) {
        float v = 0.0f;
#pragma unroll
        for (int w = 0; w < TPB / 32; w++) v += s[tid][w];
        atomicAdd(&g_acc[b][tid], (double)v);
    }
}

__device__ __forceinline__ void apply_body(const float* __restrict__ src,
                                           float* __restrict__ out,
                                           int b, int blk, int nblk, int tid) {
    __shared__ float sh_coef[12];
    if (tid == 0) {
        const double* a = g_acc[b];
        const double n = (double)NPIX;
        double mA[3] = {a[0] / n, a[1] / n, a[2] / n};
        double mB[3] = {a[3] / n, a[4] / n, a[5] / n};
        double AA[3][3];
        AA[0][0] = a[6]  - n * mA[0] * mA[0] + 0.001;
        AA[0][1] = a[7]  - n * mA[0] * mA[1];
        AA[0][2] = a[8]  - n * mA[0] * mA[2];
        AA[1][1] = a[9]  - n * mA[1] * mA[1] + 0.001;
        AA[1][2] = a[10] - n * mA[1] * mA[2];
        AA[2][2] = a[11] - n * mA[2] * mA[2] + 0.001;
        AA[1][0] = AA[0][1]; AA[2][0] = AA[0][2]; AA[2][1] = AA[1][2];
        double BA[3][3];
#pragma unroll
        for (int i = 0; i < 3; i++)
#pragma unroll
            for (int j = 0; j < 3; j++)
                BA[i][j] = a[12 + 3 * i + j] - n * mB[i] * mA[j];

        double c00 =  (AA[1][1] * AA[2][2] - AA[1][2] * AA[2][1]);
        double c01 = -(AA[1][0] * AA[2][2] - AA[1][2] * AA[2][0]);
        double c02 =  (AA[1][0] * AA[2][1] - AA[1][1] * AA[2][0]);
        double c10 = -(AA[0][1] * AA[2][2] - AA[0][2] * AA[2][1]);
        double c11 =  (AA[0][0] * AA[2][2] - AA[0][2] * AA[2][0]);
        double c12 = -(AA[0][0] * AA[2][1] - AA[0][1] * AA[2][0]);
        double c20 =  (AA[0][1] * AA[1][2] - AA[0][2] * AA[1][1]);
        double c21 = -(AA[0][0] * AA[1][2] - AA[0][2] * AA[1][0]);
        double c22 =  (AA[0][0] * AA[1][1] - AA[0][1] * AA[1][0]);
        double det = AA[0][0] * c00 + AA[0][1] * c01 + AA[0][2] * c02;
        double id = 1.0 / det;
        double inv[3][3] = {{c00 * id, c10 * id, c20 * id},
                            {c01 * id, c11 * id, c21 * id},
                            {c02 * id, c12 * id, c22 * id}};
#pragma unroll
        for (int i = 0; i < 3; i++) {
            double xi[3];
#pragma unroll
            for (int j = 0; j < 3; j++)
                xi[j] = BA[i][0] * inv[0][j] + BA[i][1] * inv[1][j] + BA[i][2] * inv[2][j];
            sh_coef[3 * i + 0] = (float)xi[0];
            sh_coef[3 * i + 1] = (float)xi[1];
            sh_coef[3 * i + 2] = (float)xi[2];
            sh_coef[9 + i] = (float)(mB[i] - (xi[0] * mA[0] + xi[1] * mA[1] + xi[2] * mA[2]));
        }
    }
    __syncthreads();

    const float x00 = sh_coef[0], x01 = sh_coef[1], x02 = sh_coef[2];
    const float x10 = sh_coef[3], x11 = sh_coef[4], x12 = sh_coef[5];
    const float x20 = sh_coef[6], x21 = sh_coef[7], x22 = sh_coef[8];
    const float o0 = sh_coef[9], o1 = sh_coef[10], o2 = sh_coef[11];

    const float4* A0 = (const float4*)(src + (size_t)b * 3 * NPIX);
    const float4* A1 = A0 + NVEC;
    const float4* A2 = A1 + NVEC;
    float4* O0 = (float4*)(out + (size_t)b * 3 * NPIX);
    float4* O1 = O0 + NVEC;
    float4* O2 = O1 + NVEC;

    const int stride = nblk * TPB;
    for (int i = blk * TPB + tid; i < NVEC; i += stride) {
        // src pinned by the previous launch's evict_last loads; .cs demotes on use
        float4 a0 = __ldcs(A0 + i), a1 = __ldcs(A1 + i), a2 = __ldcs(A2 + i);
        float4 r0, r1, r2;
#define LANE(c)                                                \
        r0.c = x00 * a0.c + x01 * a1.c + x02 * a2.c + o0;      \
        r1.c = x10 * a0.c + x11 * a1.c + x12 * a2.c + o1;      \
        r2.c = x20 * a0.c + x21 * a1.c + x22 * a2.c + o2;
        LANE(x) LANE(y) LANE(z) LANE(w)
#undef LANE
        __stcs(O0 + i, r0);
        __stcs(O1 + i, r1);
        __stcs(O2 + i, r2);
    }
}

// ---------------- kernels ----------------

// First stage: reduce group 0 only.
__global__ void __launch_bounds__(TPB, 3) reduce_kernel(const float* __restrict__ src,
                                                        const float* __restrict__ dst,
                                                        int base) {
    reduce_body(src, dst, base + blockIdx.y, blockIdx.x, (int)gridDim.x, threadIdx.x);
}

// Pipelined stage: apply group (base..base+1) overlapped with reduce of
// group (base+2..base+3). grid = (148, 3) = 444 blocks = 3/SM single wave.
//   y = 0,1 : apply batch base+y          (148 blocks, v4, ~6.9 iters)
//   y = 2   : reduce batches base+2,base+3 (74 blocks each, v8, ~6.9 iters)
__global__ void __launch_bounds__(TPB, 3) combined_kernel(const float* __restrict__ src,
                                                          const float* __restrict__ dst,
                                                          float* __restrict__ out,
                                                          int base) {
    if (blockIdx.y < 2) {
        apply_body(src, out, base + blockIdx.y, blockIdx.x, GXA, threadIdx.x);
    } else {
        const int half = (blockIdx.x >= GXR) ? 1 : 0;
        reduce_body(src, dst, base + BPG + half, blockIdx.x - half * GXR, GXR, threadIdx.x);
    }
}

// Last stage: apply final group.
__global__ void __launch_bounds__(TPB, 3) apply_kernel(const float* __restrict__ src,
                                                       float* __restrict__ out,
                                                       int base) {
    apply_body(src, out, base + blockIdx.y, blockIdx.x, (int)gridDim.x, threadIdx.x);
}

extern "C" void kernel_launch(void* const* d_in, const int* in_sizes, int n_in,
                              void* d_out, int out_size) {
    const float* src = (const float*)d_in[0];
    const float* dst = (const float*)d_in[1];
    float* out = (float*)d_out;

    zero_kernel<<<2, 256>>>();

    // Prologue: reduce batches 0..1
    dim3 rgrid(GXA, BPG);   // 148 blocks per batch, ~3.46 v8 iters (small launch)
    reduce_kernel<<<rgrid, TPB>>>(src, dst, 0);

    // Pipeline: combined(p) applies group p and reduces group p+1
    dim3 cgrid(GXA, 3);
    for (int p = 0; p < NGROUP - 1; p++)
        combined_kernel<<<cgrid, TPB>>>(src, dst, out, p * BPG);

    // Epilogue: apply final group
    dim3 agrid(GXA, BPG);
    apply_kernel<<<agrid, TPB>>>(src, out, (NGROUP - 1) * BPG);
}